// round 6
// baseline (speedup 1.0000x reference)
#include <cuda_runtime.h>

#define NN 256
#define BB 64
#define FBIG 1e8f
#define NBIG (-1e8f)
#define K2   144.269504089f     // (1/gamma) * log2(e), gamma = 0.01
#define GLN2 0.006931471806f    // gamma * ln(2)
#define CHUNK 8
#define NCHUNK 36               // 288 iters per warp per pass
#define LAG 5                   // producer chunk c+4 done at step s-1
#define STEPS (NCHUNK + LAG*3)  // 51 lockstep steps per pass (4 ladder warps)
#define FULL 0xffffffffu

// R scratch, diagonal-major per batch (coalesced along the wavefront). 16MB -> L2.
__device__ float g_R[BB * NN * NN];
__device__ float g_partV[BB];
__device__ float g_partE[BB];
__device__ unsigned g_ticket = 0;

__device__ __forceinline__ float ex2(float x) { float r; asm("ex2.approx.f32 %0, %1;" : "=f"(r) : "f"(x)); return r; }
__device__ __forceinline__ float lg2(float x) { float r; asm("lg2.approx.f32 %0, %1;" : "=f"(r) : "f"(x)); return r; }

__device__ __forceinline__ int diag_start(int d) {
    return (d <= NN + 1) ? (((d - 1) * (d - 2)) >> 1)
                         : (NN * NN - (((2 * NN + 1 - d) * (2 * NN + 2 - d)) >> 1));
}
__device__ __forceinline__ int roff(int d, int i) {
    return diag_start(d) + i - max(1, d - NN);
}

// group barrier: 128 threads of batch-group g, HW barrier id g+1
#define GBAR(g) asm volatile("bar.sync %0, 128;" :: "r"((g) + 1) : "memory")

__global__ __launch_bounds__(512, 1) void dilate_fb_kernel(
    const float* __restrict__ y_pred,
    const float* __restrict__ y_true,
    float* __restrict__ out)
{
    __shared__ float s_o[4][NN], s_t[4][NN];
    __shared__ float vrow[4][3][NN + 2];
    __shared__ float erow[4][3][NN + 2];
    __shared__ float rrow[4][3][NN + 2];
    __shared__ float s_red[4][4];
    __shared__ float s_vnn[4];
    __shared__ int   s_last[4];

    const int tid = threadIdx.x;
    const int w   = tid >> 5;
    const int l   = tid & 31;
    const int g   = w >> 2;             // batch group in block (0..3)
    const int wl  = w & 3;              // ladder warp within group (0..3)
    const int gt  = tid & 127;          // thread id within group
    const int b   = (blockIdx.x << 2) + g;
    const int i0  = (wl << 6) + 2 * l + 1;   // forward rows i0, i0+1 (1..256)
    const int i1  = i0 + 1;

    s_o[g][gt]       = y_pred[b * NN + gt];
    s_o[g][gt + 128] = y_pred[b * NN + gt + 128];
    s_t[g][gt]       = y_true[b * NN + gt];
    s_t[g][gt + 128] = y_true[b * NN + gt + 128];
    for (int x = tid; x < 4 * 3 * (NN + 2); x += 512) {
        (&vrow[0][0][0])[x] = FBIG;
        (&erow[0][0][0])[x] = 0.0f;
        (&rrow[0][0][0])[x] = NBIG;
    }
    __syncthreads();

    const float ti0 = s_t[g][i0 - 1];
    const float ti1 = s_t[g][i1 - 1];
    float* __restrict__ Rb = g_R + (size_t)b * (NN * NN);
    const float* vcons = vrow[g][(wl > 0) ? (wl - 1) : 0];
    const float* econs = erow[g][(wl > 0) ? (wl - 1) : 0];
    const float* rcons = rrow[g][(wl > 0) ? (wl - 1) : 0];

    // ================= FORWARD (2 rows/lane warp ladder, group lockstep) =========
    float vnn = 0.0f;
    {
        float v0 = FBIG, v1 = FBIG;
        float shA = FBIG, shB = FBIG;
        float lz_up = FBIG, lz_dg = FBIG;

        for (int s = 0; s < STEPS; ++s) {
            const int c = s - LAG * wl;
            if (c >= 0 && c < NCHUNK) {
                if (c == 0 && l == 0) {
                    lz_up = (wl > 0) ? vcons[1] : FBIG;
                    lz_dg = (wl == 0) ? 0.0f : FBIG;
                }
                #pragma unroll
                for (int k = 0; k < CHUNK; ++k) {
                    const int t = c * CHUNK + k;
                    const int q = t - l + 1;
                    const bool act = (unsigned)(t - l) < NN;
                    float up0 = (l == 0) ? lz_up : shA;
                    float dg0 = (l == 0) ? lz_dg : shB;
                    float oj  = s_o[g][act ? (q - 1) : 0];
                    float m0  = fminf(v0, fminf(up0, dg0));
                    float ss0 = ex2((m0 - v0) * K2) + ex2((m0 - up0) * K2)
                              + ex2((m0 - dg0) * K2);
                    float df0 = ti0 - oj;
                    float nv0 = fmaf(df0, df0, m0) - GLN2 * lg2(ss0);
                    float m1  = fminf(v1, fminf(nv0, v0));
                    float ss1 = ex2((m1 - v1) * K2) + ex2((m1 - nv0) * K2)
                              + ex2((m1 - v0) * K2);
                    float df1 = ti1 - oj;
                    float nv1 = fmaf(df1, df1, m1) - GLN2 * lg2(ss1);
                    if (!act) { nv0 = FBIG; nv1 = FBIG; }
                    if (act) {
                        int d0 = i0 + q;
                        Rb[roff(d0, i0)]     = nv0;
                        Rb[roff(d0 + 1, i1)] = nv1;
                        if (l == 31) {
                            if (wl < 3) vrow[g][wl][q] = nv1;
                            else if (q == NN) vnn = nv1;   // V[N][N]
                        }
                    }
                    float shN = __shfl_up_sync(FULL, nv1, 1);
                    shB = shA; shA = shN;
                    if (l == 0) {
                        lz_dg = lz_up;
                        int qn = t + 2; if (qn > NN + 1) qn = NN + 1;
                        lz_up = (wl > 0) ? vcons[qn] : FBIG;
                    }
                    v0 = nv0; v1 = nv1;
                }
            }
            GBAR(g);
        }
    }
    if (wl == 3 && l == 31) s_vnn[g] = vnn;

    // ================= BACKWARD as mirrored forward =================
    float sumE = 0.0f;
    {
        const int p0 = i0;
        const int iA = NN + 1 - p0;
        const int iB = iA - 1;
        int tAi = NN - p0 + 1; if (tAi > NN - 1) tAi = NN - 1;
        const float tA = s_t[g][tAi];
        const float tB = s_t[g][NN - p0];
        const float tC = s_t[g][(NN - p0 - 1 >= 0) ? (NN - p0 - 1) : 0];

        float e0 = 0.0f, e1 = 0.0f;
        float r0 = NBIG, r1 = NBIG;
        float shEA = 0.0f, shEB = 0.0f;
        float shRA = NBIG, shRB = NBIG;
        float lzE_up = 0.0f, lzE_dg = 0.0f;
        float lzR_up = NBIG, lzR_dg = NBIG;
        float oqm1 = 0.0f;
        float rcA[CHUNK], rcB[CHUNK], rnA[CHUNK], rnB[CHUNK];

        #pragma unroll
        for (int k = 0; k < CHUNK; ++k) {
            int t = k, q = t - l + 1;
            bool act = (unsigned)(t - l) < NN;
            int jg = NN + 1 - q, dA = iA + jg;
            rcA[k] = act ? __ldg(Rb + roff(dA,     iA)) : NBIG;
            rcB[k] = act ? __ldg(Rb + roff(dA - 1, iB)) : NBIG;
        }

        for (int s = 0; s < STEPS; ++s) {
            const int c = s - LAG * wl;
            if (c >= 0 && c < NCHUNK) {
                if (c + 1 < NCHUNK) {
                    #pragma unroll
                    for (int k = 0; k < CHUNK; ++k) {
                        int t = (c + 1) * CHUNK + k, q = t - l + 1;
                        bool act = (unsigned)(t - l) < NN;
                        int jg = NN + 1 - q, dA = iA + jg;
                        rnA[k] = act ? __ldg(Rb + roff(dA,     iA)) : NBIG;
                        rnB[k] = act ? __ldg(Rb + roff(dA - 1, iB)) : NBIG;
                    }
                }
                if (c == 0 && l == 0) {
                    lzE_up = (wl > 0) ? econs[1] : 0.0f;
                    lzR_up = (wl > 0) ? rcons[1] : NBIG;
                    lzE_dg = 0.0f; lzR_dg = NBIG;
                }
                #pragma unroll
                for (int k = 0; k < CHUNK; ++k) {
                    const int t = c * CHUNK + k;
                    const int q = t - l + 1;
                    const bool act = (unsigned)(t - l) < NN;
                    float Eup = (l == 0) ? lzE_up : shEA;
                    float Rup = (l == 0) ? lzR_up : shRA;
                    float Edg = (l == 0) ? lzE_dg : shEB;
                    float Rdg = (l == 0) ? lzR_dg : shRB;
                    float oq  = s_o[g][act ? (NN - q) : 0];
                    float RA  = rcA[k];
                    float RB  = rcB[k];
                    float dA0 = tA - oq,   dB0 = tB - oqm1, dC0 = tA - oqm1;
                    float ne0 = ex2(fmaf(-dA0, dA0, Rup - RA) * K2) * Eup
                              + ex2(fmaf(-dB0, dB0, r0  - RA) * K2) * e0
                              + ex2(fmaf(-dC0, dC0, Rdg - RA) * K2) * Edg;
                    if (wl == 0 && l == 0 && t == 0) ne0 = 1.0f;   // E[N][N]
                    float dA1 = tB - oq,   dB1 = tC - oqm1, dC1 = tB - oqm1;
                    float ne1 = ex2(fmaf(-dA1, dA1, RA - RB) * K2) * ne0
                              + ex2(fmaf(-dB1, dB1, r1 - RB) * K2) * e1
                              + ex2(fmaf(-dC1, dC1, r0 - RB) * K2) * e0;
                    if (!act) { ne0 = 0.0f; ne1 = 0.0f; RA = NBIG; RB = NBIG; }
                    float wq0 = (float)(q - p0);
                    sumE = fmaf(ne0, wq0 * wq0, sumE);
                    float wq1 = wq0 - 1.0f;
                    sumE = fmaf(ne1, wq1 * wq1, sumE);
                    if (act && l == 31 && wl < 3) { erow[g][wl][q] = ne1; rrow[g][wl][q] = RB; }
                    float shEN = __shfl_up_sync(FULL, ne1, 1);
                    float shRN = __shfl_up_sync(FULL, RB, 1);
                    shEB = shEA; shEA = shEN;
                    shRB = shRA; shRA = shRN;
                    if (l == 0) {
                        lzE_dg = lzE_up; lzR_dg = lzR_up;
                        int qn = t + 2; if (qn > NN + 1) qn = NN + 1;
                        lzE_up = (wl > 0) ? econs[qn] : 0.0f;
                        lzR_up = (wl > 0) ? rcons[qn] : NBIG;
                    }
                    e0 = ne0; r0 = RA; e1 = ne1; r1 = RB; oqm1 = oq;
                }
                #pragma unroll
                for (int k = 0; k < CHUNK; ++k) { rcA[k] = rnA[k]; rcB[k] = rnB[k]; }
            }
            GBAR(g);
        }
    }

    // ---- group reduce of sum(E * omega) ----
    #pragma unroll
    for (int off = 16; off > 0; off >>= 1)
        sumE += __shfl_down_sync(FULL, sumE, off);
    if (l == 0) s_red[g][wl] = sumE;
    GBAR(g);

    // ---- per-group partials + deterministic last-group finalize ----
    if (wl == 0 && l == 0) {
        g_partV[b] = s_vnn[g];
        g_partE[b] = s_red[g][0] + s_red[g][1] + s_red[g][2] + s_red[g][3];
        __threadfence();
        unsigned tk = atomicAdd(&g_ticket, 1u);
        s_last[g] = (tk == BB - 1) ? 1 : 0;
    }
    GBAR(g);
    if (s_last[g] && wl == 0) {
        __threadfence();
        float sv = __ldcg(&g_partV[l]) + __ldcg(&g_partV[l + 32]);
        float se = __ldcg(&g_partE[l]) + __ldcg(&g_partE[l + 32]);
        #pragma unroll
        for (int off = 16; off > 0; off >>= 1) {
            sv += __shfl_down_sync(FULL, sv, off);
            se += __shfl_down_sync(FULL, se, off);
        }
        if (l == 0) {
            float loss_shape    = sv * (1.0f / (float)BB);
            float loss_temporal = se * (1.0f / ((float)BB * (float)(NN * NN)));
            out[0] = 0.5f * loss_shape + 0.5f * loss_temporal;
            g_ticket = 0;   // reset for graph replay
        }
    }
}

extern "C" void kernel_launch(void* const* d_in, const int* in_sizes, int n_in,
                              void* d_out, int out_size) {
    const float* y_pred = (const float*)d_in[0];
    const float* y_true = (const float*)d_in[1];
    dilate_fb_kernel<<<BB / 4, 512>>>(y_pred, y_true, (float*)d_out);
}

// round 7
// speedup vs baseline: 1.8699x; 1.8699x over previous
#include <cuda_runtime.h>

#define NN 256
#define BB 64
#define FBIG 1e8f
#define NBIG (-1e8f)
#define K2   144.269504089f     // (1/gamma) * log2(e), gamma = 0.01
#define GLN2 0.006931471806f    // gamma * ln(2)
#define CHUNK 8
#define NCHUNK 36               // 288 iters per warp per pass
#define LAG 5                   // producer chunk c+4 done at step s-1
#define STEPS (NCHUNK + LAG*3)  // 51 lockstep steps per pass (4 warps)
#define FULL 0xffffffffu

// R scratch, diagonal-major per batch (coalesced along the wavefront). 16MB -> L2.
__device__ float g_R[BB * NN * NN];
__device__ float g_partV[BB];
__device__ float g_partE[BB];
__device__ unsigned g_ticket = 0;

__device__ __forceinline__ float ex2(float x) { float r; asm("ex2.approx.f32 %0, %1;" : "=f"(r) : "f"(x)); return r; }
__device__ __forceinline__ float lg2(float x) { float r; asm("lg2.approx.f32 %0, %1;" : "=f"(r) : "f"(x)); return r; }

__device__ __forceinline__ int diag_start(int d) {
    return (d <= NN + 1) ? (((d - 1) * (d - 2)) >> 1)
                         : (NN * NN - (((2 * NN + 1 - d) * (2 * NN + 2 - d)) >> 1));
}
__device__ __forceinline__ int roff(int d, int i) {
    return diag_start(d) + i - max(1, d - NN);
}

__global__ __launch_bounds__(128, 1) void dilate_fb_kernel(
    const float* __restrict__ y_pred,
    const float* __restrict__ y_true,
    float* __restrict__ out)
{
    __shared__ float s_o[NN], s_t[NN];
    __shared__ float vrow[3][NN + 2];   // forward boundary rows V[64(w+1)][q]
    __shared__ float erow[3][NN + 2];   // backward boundary rows E'
    __shared__ float rrow[3][NN + 2];   // backward boundary rows R'
    __shared__ float s_red[4];
    __shared__ int   s_last;

    const int b   = blockIdx.x;
    const int tid = threadIdx.x;
    const int w   = tid >> 5;
    const int l   = tid & 31;
    const int i0  = (w << 6) + 2 * l + 1;   // forward rows i0, i0+1 (1..256)
    const int i1  = i0 + 1;

    s_o[tid]       = y_pred[b * NN + tid];
    s_o[tid + 128] = y_pred[b * NN + tid + 128];
    s_t[tid]       = y_true[b * NN + tid];
    s_t[tid + 128] = y_true[b * NN + tid + 128];
    for (int x = tid; x < 3 * (NN + 2); x += 128) {
        (&vrow[0][0])[x] = FBIG;
        (&erow[0][0])[x] = 0.0f;
        (&rrow[0][0])[x] = NBIG;
    }
    __syncthreads();

    const float ti0 = s_t[i0 - 1];
    const float ti1 = s_t[i1 - 1];
    float* __restrict__ Rb = g_R + (size_t)b * (NN * NN);
    const float* vcons = vrow[(w > 0) ? (w - 1) : 0];
    const float* econs = erow[(w > 0) ? (w - 1) : 0];
    const float* rcons = rrow[(w > 0) ? (w - 1) : 0];

    // ========== FORWARD: (m,w) soft-min — linear w-recurrence, short m-chain =====
    // V = m - GLN2*lg2(w). Neighbors handed over pre-folded (V-domain, w=1).
    float vnn = 0.0f;
    {
        float m0 = FBIG, w0 = 1.0f;     // own left state row i0
        float m1 = FBIG, w1 = 1.0f;     // own left state row i1
        float shA = FBIG, shB = FBIG;   // lane l-1 row-2 V values (t-1, t-2)
        float lz_up = FBIG, lz_dg = FBIG;
        float R0 = FBIG, R1 = FBIG;     // last stored V values (for chunk-end fold)

        for (int s = 0; s < STEPS; ++s) {
            const int c = s - LAG * w;
            if (c >= 0 && c < NCHUNK) {
                if (c == 0 && l == 0) {
                    lz_up = (w > 0) ? vcons[1] : FBIG;
                    lz_dg = (w == 0) ? 0.0f : FBIG;    // V[0][0]=0 only for (1,1)
                }
                #pragma unroll
                for (int k = 0; k < CHUNK; ++k) {
                    const int t = c * CHUNK + k;
                    const int q = t - l + 1;
                    const bool act = (unsigned)(t - l) < NN;
                    float up0 = (l == 0) ? lz_up : shA;   // V[i0-1][q]   (folded)
                    float dg0 = (l == 0) ? lz_dg : shB;   // V[i0-1][q-1] (folded)
                    float oj  = s_o[act ? (q - 1) : 0];
                    float om0 = m0, ow0 = w0;             // row-2 diag = old row-1
                    // ---- row 1 ----
                    float ms0 = fminf(m0, fminf(up0, dg0));       // m-chain
                    float el0 = ex2((ms0 - m0)  * K2);            // off-chain
                    float eu0 = ex2((ms0 - up0) * K2);
                    float ed0 = ex2((ms0 - dg0) * K2);
                    float nw0 = fmaf(w0, el0, eu0 + ed0);         // w-chain (fma)
                    float df0 = ti0 - oj;
                    float nm0 = fmaf(df0, df0, ms0);              // m-chain
                    // ---- row 2: up = (nm0,nw0), diag = (om0,ow0) ----
                    float ms1 = fminf(m1, fminf(nm0, om0));
                    float el1 = ex2((ms1 - m1)  * K2);
                    float eu1 = ex2((ms1 - nm0) * K2);
                    float ed1 = ex2((ms1 - om0) * K2);
                    float nw1 = fmaf(w1, el1, fmaf(nw0, eu1, ow0 * ed1));
                    float df1 = ti1 - oj;
                    float nm1 = fmaf(df1, df1, ms1);
                    // ---- fold to V for store / handoff (off the recurrence chain)
                    R0 = fmaf(-GLN2, lg2(nw0), nm0);
                    R1 = fmaf(-GLN2, lg2(nw1), nm1);
                    if (!act) { nm0 = FBIG; nw0 = 1.0f; nm1 = FBIG; nw1 = 1.0f;
                                R0 = FBIG; R1 = FBIG; }
                    if (act) {
                        int d0 = i0 + q;
                        Rb[roff(d0, i0)]     = R0;
                        Rb[roff(d0 + 1, i1)] = R1;
                        if (l == 31) {
                            if (w < 3) vrow[w][q] = R1;
                            else if (q == NN) vnn = R1;   // V[N][N]
                        }
                    }
                    float shN = __shfl_up_sync(FULL, R1, 1);
                    shB = shA; shA = shN;
                    if (l == 0) {
                        lz_dg = lz_up;
                        int qn = t + 2; if (qn > NN + 1) qn = NN + 1;
                        lz_up = (w > 0) ? vcons[qn] : FBIG;
                    }
                    m0 = nm0; w0 = nw0; m1 = nm1; w1 = nw1;
                }
                // chunk-end fold: reuse stored V values (free renormalization)
                m0 = R0; w0 = 1.0f; m1 = R1; w1 = 1.0f;
            }
            __syncthreads();
        }
    }
    if (w == 3 && l == 31) g_partV[b] = vnn;

    // ================= BACKWARD as mirrored forward (unchanged from R5) ==========
    float sumE = 0.0f;
    {
        const int p0 = i0;
        const int iA = NN + 1 - p0;
        const int iB = iA - 1;
        int tAi = NN - p0 + 1; if (tAi > NN - 1) tAi = NN - 1;
        const float tA = s_t[tAi];
        const float tB = s_t[NN - p0];
        const float tC = s_t[(NN - p0 - 1 >= 0) ? (NN - p0 - 1) : 0];

        float e0 = 0.0f, e1 = 0.0f;
        float r0 = NBIG, r1 = NBIG;
        float shEA = 0.0f, shEB = 0.0f;
        float shRA = NBIG, shRB = NBIG;
        float lzE_up = 0.0f, lzE_dg = 0.0f;
        float lzR_up = NBIG, lzR_dg = NBIG;
        float oqm1 = 0.0f;
        float rcA[CHUNK], rcB[CHUNK], rnA[CHUNK], rnB[CHUNK];

        #pragma unroll
        for (int k = 0; k < CHUNK; ++k) {
            int t = k, q = t - l + 1;
            bool act = (unsigned)(t - l) < NN;
            int jg = NN + 1 - q, dA = iA + jg;
            rcA[k] = act ? __ldg(Rb + roff(dA,     iA)) : NBIG;
            rcB[k] = act ? __ldg(Rb + roff(dA - 1, iB)) : NBIG;
        }

        for (int s = 0; s < STEPS; ++s) {
            const int c = s - LAG * w;
            if (c >= 0 && c < NCHUNK) {
                if (c + 1 < NCHUNK) {
                    #pragma unroll
                    for (int k = 0; k < CHUNK; ++k) {
                        int t = (c + 1) * CHUNK + k, q = t - l + 1;
                        bool act = (unsigned)(t - l) < NN;
                        int jg = NN + 1 - q, dA = iA + jg;
                        rnA[k] = act ? __ldg(Rb + roff(dA,     iA)) : NBIG;
                        rnB[k] = act ? __ldg(Rb + roff(dA - 1, iB)) : NBIG;
                    }
                }
                if (c == 0 && l == 0) {
                    lzE_up = (w > 0) ? econs[1] : 0.0f;
                    lzR_up = (w > 0) ? rcons[1] : NBIG;
                    lzE_dg = 0.0f; lzR_dg = NBIG;
                }
                #pragma unroll
                for (int k = 0; k < CHUNK; ++k) {
                    const int t = c * CHUNK + k;
                    const int q = t - l + 1;
                    const bool act = (unsigned)(t - l) < NN;
                    float Eup = (l == 0) ? lzE_up : shEA;
                    float Rup = (l == 0) ? lzR_up : shRA;
                    float Edg = (l == 0) ? lzE_dg : shEB;
                    float Rdg = (l == 0) ? lzR_dg : shRB;
                    float oq  = s_o[act ? (NN - q) : 0];
                    float RA  = rcA[k];
                    float RB  = rcB[k];
                    float dA0 = tA - oq,   dB0 = tB - oqm1, dC0 = tA - oqm1;
                    float ne0 = ex2(fmaf(-dA0, dA0, Rup - RA) * K2) * Eup
                              + ex2(fmaf(-dB0, dB0, r0  - RA) * K2) * e0
                              + ex2(fmaf(-dC0, dC0, Rdg - RA) * K2) * Edg;
                    if (w == 0 && l == 0 && t == 0) ne0 = 1.0f;   // E[N][N]
                    float dA1 = tB - oq,   dB1 = tC - oqm1, dC1 = tB - oqm1;
                    float ne1 = ex2(fmaf(-dA1, dA1, RA - RB) * K2) * ne0
                              + ex2(fmaf(-dB1, dB1, r1 - RB) * K2) * e1
                              + ex2(fmaf(-dC1, dC1, r0 - RB) * K2) * e0;
                    if (!act) { ne0 = 0.0f; ne1 = 0.0f; RA = NBIG; RB = NBIG; }
                    float wq0 = (float)(q - p0);
                    sumE = fmaf(ne0, wq0 * wq0, sumE);
                    float wq1 = wq0 - 1.0f;
                    sumE = fmaf(ne1, wq1 * wq1, sumE);
                    if (act && l == 31 && w < 3) { erow[w][q] = ne1; rrow[w][q] = RB; }
                    float shEN = __shfl_up_sync(FULL, ne1, 1);
                    float shRN = __shfl_up_sync(FULL, RB, 1);
                    shEB = shEA; shEA = shEN;
                    shRB = shRA; shRA = shRN;
                    if (l == 0) {
                        lzE_dg = lzE_up; lzR_dg = lzR_up;
                        int qn = t + 2; if (qn > NN + 1) qn = NN + 1;
                        lzE_up = (w > 0) ? econs[qn] : 0.0f;
                        lzR_up = (w > 0) ? rcons[qn] : NBIG;
                    }
                    e0 = ne0; r0 = RA; e1 = ne1; r1 = RB; oqm1 = oq;
                }
                #pragma unroll
                for (int k = 0; k < CHUNK; ++k) { rcA[k] = rnA[k]; rcB[k] = rnB[k]; }
            }
            __syncthreads();
        }
    }

    // ---- reduce sum(E * omega) ----
    #pragma unroll
    for (int off = 16; off > 0; off >>= 1)
        sumE += __shfl_down_sync(FULL, sumE, off);
    if (l == 0) s_red[w] = sumE;
    __syncthreads();

    if (tid == 0) {
        g_partE[b] = s_red[0] + s_red[1] + s_red[2] + s_red[3];
        __threadfence();
        unsigned tk = atomicAdd(&g_ticket, 1u);
        s_last = (tk == BB - 1) ? 1 : 0;
    }
    __syncthreads();
    if (s_last && tid < 32) {
        __threadfence();
        float sv = __ldcg(&g_partV[tid]) + __ldcg(&g_partV[tid + 32]);
        float se = __ldcg(&g_partE[tid]) + __ldcg(&g_partE[tid + 32]);
        #pragma unroll
        for (int off = 16; off > 0; off >>= 1) {
            sv += __shfl_down_sync(FULL, sv, off);
            se += __shfl_down_sync(FULL, se, off);
        }
        if (tid == 0) {
            float loss_shape    = sv * (1.0f / (float)BB);
            float loss_temporal = se * (1.0f / ((float)BB * (float)(NN * NN)));
            out[0] = 0.5f * loss_shape + 0.5f * loss_temporal;
            g_ticket = 0;   // reset for graph replay
        }
    }
}

extern "C" void kernel_launch(void* const* d_in, const int* in_sizes, int n_in,
                              void* d_out, int out_size) {
    const float* y_pred = (const float*)d_in[0];
    const float* y_true = (const float*)d_in[1];
    dilate_fb_kernel<<<BB, 128>>>(y_pred, y_true, (float*)d_out);
}

// round 9
// speedup vs baseline: 2.1685x; 1.1597x over previous
#include <cuda_runtime.h>

#define NN 256
#define BB 64
#define FBIG 1e8f
#define NBIG (-1e8f)
#define K2   144.269504089f     // (1/gamma) * log2(e), gamma = 0.01
#define GLN2 0.006931471806f    // gamma * ln(2)
#define CHUNK 8
#define NCHUNK 36               // ceil(287/8): 288 iters per warp per pass
#define LAG 5                   // producer chunk c+4 done at step s-1 (W=2)
#define STEPS (NCHUNK + LAG)    // 41 lockstep steps per pass
#define FULL 0xffffffffu

// R scratch: [batch][group][col] float4, group = 4-row band (rows 4g+1..4g+4),
// col index = original column - 1. One STG.128 per forward iter, one LDG.128
// per backward iter (mirror group, mirrored column). 16 MB -> L2-resident.
__device__ float4 g_R4[BB * 64 * NN];
__device__ float g_partV[BB];
__device__ float g_partE[BB];
__device__ unsigned g_ticket = 0;

__device__ __forceinline__ float ex2(float x) { float r; asm("ex2.approx.f32 %0, %1;" : "=f"(r) : "f"(x)); return r; }
__device__ __forceinline__ float lg2(float x) { float r; asm("lg2.approx.f32 %0, %1;" : "=f"(r) : "f"(x)); return r; }

__global__ __launch_bounds__(64, 1) void dilate_fb_kernel(
    const float* __restrict__ y_pred,
    const float* __restrict__ y_true,
    float* __restrict__ out)
{
    __shared__ float s_o[NN], s_t[NN];
    __shared__ float vrow[NN + 2];   // forward boundary row V[128][q]
    __shared__ float erow[NN + 2];   // backward boundary row E'[128][q]
    __shared__ float rrow[NN + 2];   // backward boundary row R'[128][q]
    __shared__ float s_red[2];
    __shared__ float s_vnn;
    __shared__ int   s_last;

    const int b   = blockIdx.x;
    const int tid = threadIdx.x;
    const int w   = tid >> 5;
    const int l   = tid & 31;
    const int i0  = (w << 7) + (l << 2) + 1;  // forward rows i0..i0+3
    const int gf  = (w << 5) + l;             // forward group
    const int gb  = 63 - gf;                  // backward mirror group

    for (int x = tid; x < NN; x += 64) {
        s_o[x] = y_pred[b * NN + x];
        s_t[x] = y_true[b * NN + x];
    }
    for (int x = tid; x < NN + 2; x += 64) {
        vrow[x] = FBIG; erow[x] = 0.0f; rrow[x] = NBIG;
    }
    __syncthreads();

    const float ti0 = s_t[i0 - 1], ti1 = s_t[i0], ti2 = s_t[i0 + 1], ti3 = s_t[i0 + 2];
    float4* __restrict__ Rb = g_R4 + (size_t)b * (64 * NN);

    // ================= FORWARD: (m,w) soft-min, 4 rows/lane =================
    // lane l at iter t computes col q = t-l+1 for its 4 rows; rows chain in-iter.
    {
        float mm0 = FBIG, mm1 = FBIG, mm2 = FBIG, mm3 = FBIG;
        float ww0 = 1.0f, ww1 = 1.0f, ww2 = 1.0f, ww3 = 1.0f;
        float Rf0 = FBIG, Rf1 = FBIG, Rf2 = FBIG, Rf3 = FBIG;
        float shA = FBIG, shB = FBIG, lz_up = FBIG, lz_dg = FBIG;

        for (int s = 0; s < STEPS; ++s) {
            const int c = s - LAG * w;
            if (c >= 0 && c < NCHUNK) {
                if (c == 0 && l == 0) { lz_up = (w > 0) ? vrow[1] : FBIG; lz_dg = FBIG; }
                float4* pst = Rb + gf * NN + (c * CHUNK - l);
                #pragma unroll
                for (int k = 0; k < CHUNK; ++k) {
                    const int t = c * CHUNK + k;
                    const int q = t - l + 1;
                    const bool act   = (unsigned)(t - l) < NN;
                    const bool first = (t == l);
                    if (first) { mm0 = FBIG; mm1 = FBIG; mm2 = FBIG; mm3 = FBIG;
                                 ww0 = 1.0f; ww1 = 1.0f; ww2 = 1.0f; ww3 = 1.0f; }
                    float up0 = (l == 0) ? lz_up : shA;       // V[i0-1][q]   (folded)
                    float dg0 = (l == 0) ? lz_dg : shB;       // V[i0-1][q-1] (folded)
                    if (first) dg0 = (i0 == 1) ? 0.0f : FBIG; // V[0][0]=0 boundary
                    float oj = s_o[act ? (q - 1) : 0];
                    // row0 (neighbors folded, weight 1)
                    float ms0 = fminf(mm0, fminf(up0, dg0));
                    float nw0 = fmaf(ww0, ex2((ms0 - mm0) * K2),
                                     ex2((ms0 - up0) * K2) + ex2((ms0 - dg0) * K2));
                    float df0 = ti0 - oj;
                    float nm0 = fmaf(df0, df0, ms0);
                    // row1: up = (nm0,nw0) cur, diag = (mm0,ww0) old
                    float ms1 = fminf(mm1, fminf(nm0, mm0));
                    float nw1 = fmaf(ww1, ex2((ms1 - mm1) * K2),
                                fmaf(nw0, ex2((ms1 - nm0) * K2), ww0 * ex2((ms1 - mm0) * K2)));
                    float df1 = ti1 - oj;
                    float nm1 = fmaf(df1, df1, ms1);
                    // row2
                    float ms2 = fminf(mm2, fminf(nm1, mm1));
                    float nw2 = fmaf(ww2, ex2((ms2 - mm2) * K2),
                                fmaf(nw1, ex2((ms2 - nm1) * K2), ww1 * ex2((ms2 - mm1) * K2)));
                    float df2 = ti2 - oj;
                    float nm2 = fmaf(df2, df2, ms2);
                    // row3
                    float ms3 = fminf(mm3, fminf(nm2, mm2));
                    float nw3 = fmaf(ww3, ex2((ms3 - mm3) * K2),
                                fmaf(nw2, ex2((ms3 - nm2) * K2), ww2 * ex2((ms3 - mm2) * K2)));
                    float df3 = ti3 - oj;
                    float nm3 = fmaf(df3, df3, ms3);
                    // fold to V (off the m-chain)
                    Rf0 = fmaf(-GLN2, lg2(nw0), nm0);
                    Rf1 = fmaf(-GLN2, lg2(nw1), nm1);
                    Rf2 = fmaf(-GLN2, lg2(nw2), nm2);
                    Rf3 = fmaf(-GLN2, lg2(nw3), nm3);
                    if (!act) { Rf0 = FBIG; Rf1 = FBIG; Rf2 = FBIG; Rf3 = FBIG; }
                    if (act) {
                        pst[k] = make_float4(Rf0, Rf1, Rf2, Rf3);
                        if (w == 0 && l == 31) vrow[q] = Rf3;
                        if (w == 1 && l == 31 && q == NN) s_vnn = Rf3;  // V[N][N]
                    }
                    float shN = __shfl_up_sync(FULL, Rf3, 1);
                    shB = shA; shA = shN;
                    if (l == 0) {
                        lz_dg = lz_up;
                        int qn = t + 2; if (qn > NN + 1) qn = NN + 1;
                        lz_up = (w > 0) ? vrow[qn] : FBIG;
                    }
                    mm0 = nm0; ww0 = nw0; mm1 = nm1; ww1 = nw1;
                    mm2 = nm2; ww2 = nw2; mm3 = nm3; ww3 = nw3;
                }
                // chunk-end renormalize: m <- folded V, w <- 1
                mm0 = Rf0; mm1 = Rf1; mm2 = Rf2; mm3 = Rf3;
                ww0 = 1.0f; ww1 = 1.0f; ww2 = 1.0f; ww3 = 1.0f;
            }
            __syncthreads();
        }
    }

    // ================= BACKWARD: mirrored forward, 4 rows/lane =================
    // Reversed coords p=N+1-i, q'=N+1-j; lane owns p0..p0+3 (p0=i0 formula),
    // orig rows = mirror group gb; float4 comp for row p0+r is [3-r]; the R
    // column for reversed col q' is the MIRRORED index NN-1-(t-l) (orig j-1).
    float sumE = 0.0f;
    {
        const int p0 = i0;
        const float tP0 = s_t[NN - p0];
        const float tP1 = s_t[NN - p0 - 1];
        const float tP2 = s_t[NN - p0 - 2];
        const float tP3 = s_t[NN - p0 - 3];
        int tU0i = NN - p0 + 1; if (tU0i > NN - 1) tU0i = NN - 1;
        const float tU0 = s_t[tU0i];   // T(p0-1); value unused when p0==1

        float e0 = 0, e1 = 0, e2 = 0, e3 = 0;
        float r0 = NBIG, r1 = NBIG, r2 = NBIG, r3 = NBIG;
        float shEA = 0, shEB = 0, shRA = NBIG, shRB = NBIG;
        float lzE_up = 0, lzE_dg = 0, lzR_up = NBIG, lzR_dg = NBIG;
        float oqm1 = 0.0f;
        float4 rc[CHUNK], rn[CHUNK];
        const float4* __restrict__ pld = Rb + gb * NN;

        #pragma unroll
        for (int k = 0; k < CHUNK; ++k) {   // prefetch chunk 0 (mirrored col)
            int t = k; bool a = (unsigned)(t - l) < NN;
            rc[k] = a ? __ldg(pld + (NN - 1 - (t - l)))
                      : make_float4(NBIG, NBIG, NBIG, NBIG);
        }

        for (int s = 0; s < STEPS; ++s) {
            const int c = s - LAG * w;
            if (c >= 0 && c < NCHUNK) {
                if (c + 1 < NCHUNK) {       // prefetch next chunk (overlaps compute)
                    #pragma unroll
                    for (int k = 0; k < CHUNK; ++k) {
                        int t = (c + 1) * CHUNK + k; bool a = (unsigned)(t - l) < NN;
                        rn[k] = a ? __ldg(pld + (NN - 1 - (t - l)))
                                  : make_float4(NBIG, NBIG, NBIG, NBIG);
                    }
                }
                if (c == 0 && l == 0) {
                    lzE_up = (w > 0) ? erow[1] : 0.0f;
                    lzR_up = (w > 0) ? rrow[1] : NBIG;
                    lzE_dg = 0.0f; lzR_dg = NBIG;
                }
                #pragma unroll
                for (int k = 0; k < CHUNK; ++k) {
                    const int t = c * CHUNK + k;
                    const int q = t - l + 1;
                    const bool act   = (unsigned)(t - l) < NN;
                    const bool first = (t == l);
                    if (first) { e0 = e1 = e2 = e3 = 0.0f; r0 = r1 = r2 = r3 = NBIG; }
                    float Eu0 = (l == 0) ? lzE_up : shEA;
                    float Ru0 = (l == 0) ? lzR_up : shRA;
                    float Ed0 = (l == 0) ? lzE_dg : shEB;
                    float Rd0 = (l == 0) ? lzR_dg : shRB;
                    if (first) { Ed0 = 0.0f; Rd0 = NBIG; }
                    float oq = s_o[act ? (NN - q) : 0];
                    float4 Rc = rc[k];
                    float Rc0 = Rc.w, Rc1 = Rc.z, Rc2 = Rc.y, Rc3 = Rc.x;
                    // row0 (p0)
                    float dU0 = tU0 - oq, dL0 = tP0 - oqm1, dD0 = tU0 - oqm1;
                    float ne0 = ex2(fmaf(-dU0, dU0, Ru0 - Rc0) * K2) * Eu0
                              + ex2(fmaf(-dL0, dL0, r0  - Rc0) * K2) * e0
                              + ex2(fmaf(-dD0, dD0, Rd0 - Rc0) * K2) * Ed0;
                    if (w == 0 && l == 0 && t == 0) ne0 = 1.0f;   // E[N][N]
                    // row1: up = (Rc0, ne0) cur; diag = (r0, e0) old
                    float dU1 = tP0 - oq, dL1 = tP1 - oqm1, dD1 = tP0 - oqm1;
                    float ne1 = ex2(fmaf(-dU1, dU1, Rc0 - Rc1) * K2) * ne0
                              + ex2(fmaf(-dL1, dL1, r1  - Rc1) * K2) * e1
                              + ex2(fmaf(-dD1, dD1, r0  - Rc1) * K2) * e0;
                    // row2
                    float dU2 = tP1 - oq, dL2 = tP2 - oqm1, dD2 = tP1 - oqm1;
                    float ne2 = ex2(fmaf(-dU2, dU2, Rc1 - Rc2) * K2) * ne1
                              + ex2(fmaf(-dL2, dL2, r2  - Rc2) * K2) * e2
                              + ex2(fmaf(-dD2, dD2, r1  - Rc2) * K2) * e1;
                    // row3
                    float dU3 = tP2 - oq, dL3 = tP3 - oqm1, dD3 = tP2 - oqm1;
                    float ne3 = ex2(fmaf(-dU3, dU3, Rc2 - Rc3) * K2) * ne2
                              + ex2(fmaf(-dL3, dL3, r3  - Rc3) * K2) * e3
                              + ex2(fmaf(-dD3, dD3, r2  - Rc3) * K2) * e2;
                    if (!act) { ne0 = 0; ne1 = 0; ne2 = 0; ne3 = 0; }
                    if (act) {
                        float wq = (float)(q - p0);         // (i-j) = q'-p
                        sumE = fmaf(ne0, wq * wq, sumE);
                        float w1_ = wq - 1.0f; sumE = fmaf(ne1, w1_ * w1_, sumE);
                        float w2_ = wq - 2.0f; sumE = fmaf(ne2, w2_ * w2_, sumE);
                        float w3_ = wq - 3.0f; sumE = fmaf(ne3, w3_ * w3_, sumE);
                        if (w == 0 && l == 31) { erow[q] = ne3; rrow[q] = Rc3; }
                    }
                    float shEN = __shfl_up_sync(FULL, ne3, 1);
                    float shRN = __shfl_up_sync(FULL, Rc3, 1);
                    shEB = shEA; shEA = shEN;
                    shRB = shRA; shRA = shRN;
                    if (l == 0) {
                        lzE_dg = lzE_up; lzR_dg = lzR_up;
                        int qn = t + 2; if (qn > NN + 1) qn = NN + 1;
                        lzE_up = (w > 0) ? erow[qn] : 0.0f;
                        lzR_up = (w > 0) ? rrow[qn] : NBIG;
                    }
                    e0 = ne0; e1 = ne1; e2 = ne2; e3 = ne3;
                    r0 = Rc0; r1 = Rc1; r2 = Rc2; r3 = Rc3;
                    oqm1 = oq;
                }
                #pragma unroll
                for (int k = 0; k < CHUNK; ++k) rc[k] = rn[k];
            }
            __syncthreads();
        }
    }

    // ---- reduce sum(E * omega): warp trees + 2 partials ----
    #pragma unroll
    for (int off = 16; off > 0; off >>= 1)
        sumE += __shfl_down_sync(FULL, sumE, off);
    if (l == 0) s_red[w] = sumE;
    __syncthreads();

    if (tid == 0) {
        g_partV[b] = s_vnn;
        g_partE[b] = s_red[0] + s_red[1];
        __threadfence();
        unsigned tk = atomicAdd(&g_ticket, 1u);
        s_last = (tk == BB - 1) ? 1 : 0;
    }
    __syncthreads();
    if (s_last && tid < 32) {
        __threadfence();
        float sv = __ldcg(&g_partV[tid]) + __ldcg(&g_partV[tid + 32]);
        float se = __ldcg(&g_partE[tid]) + __ldcg(&g_partE[tid + 32]);
        #pragma unroll
        for (int off = 16; off > 0; off >>= 1) {
            sv += __shfl_down_sync(FULL, sv, off);
            se += __shfl_down_sync(FULL, se, off);
        }
        if (tid == 0) {
            float loss_shape    = sv * (1.0f / (float)BB);
            float loss_temporal = se * (1.0f / ((float)BB * (float)(NN * NN)));
            out[0] = 0.5f * loss_shape + 0.5f * loss_temporal;
            g_ticket = 0;   // reset for graph replay
        }
    }
}

extern "C" void kernel_launch(void* const* d_in, const int* in_sizes, int n_in,
                              void* d_out, int out_size) {
    const float* y_pred = (const float*)d_in[0];
    const float* y_true = (const float*)d_in[1];
    dilate_fb_kernel<<<BB, 64>>>(y_pred, y_true, (float*)d_out);
}

// round 10
// speedup vs baseline: 2.2632x; 1.0436x over previous
#include <cuda_runtime.h>

#define NN 256
#define BB 64
#define FBIG 1e8f
#define NBIG (-1e8f)
#define K2   144.269504089f     // (1/gamma) * log2(e), gamma = 0.01
#define GLN2 0.006931471806f    // gamma * ln(2)
#define TT   288                // padded iteration count (per pass)
#define FULL 0xffffffffu

// R scratch, skew-coalesced: chunk index (col+group)*32 + group, each chunk =
// 8 rows (2 float4). At any iteration all 32 lanes hit one contiguous 1KB line
// (forward store AND backward load). ~18.9 MB -> L2-resident.
__device__ float4 g_R8[BB * TT * 32 * 2];
__device__ float g_partV[BB];
__device__ float g_partE[BB];
__device__ unsigned g_ticket = 0;

__device__ __forceinline__ float ex2(float x) { float r; asm("ex2.approx.f32 %0, %1;" : "=f"(r) : "f"(x)); return r; }
__device__ __forceinline__ float lg2(float x) { float r; asm("lg2.approx.f32 %0, %1;" : "=f"(r) : "f"(x)); return r; }

__global__ __launch_bounds__(32, 1) void dilate_fb_kernel(
    const float* __restrict__ y_pred,
    const float* __restrict__ y_true,
    float* __restrict__ out)
{
    __shared__ float s_o[NN], s_t[NN];

    const int b = blockIdx.x;
    const int l = threadIdx.x;          // lane; owns rows 8l+1 .. 8l+8

    for (int x = l; x < NN; x += 32) {
        s_o[x] = y_pred[b * NN + x];
        s_t[x] = y_true[b * NN + x];
    }
    __syncwarp();

    float ti[8];
    #pragma unroll
    for (int r = 0; r < 8; ++r) ti[r] = s_t[8 * l + r];

    float4* __restrict__ Rbase = g_R8 + (size_t)b * (TT * 32 * 2);

    // ================= FORWARD: (m,w) soft-min, 8 rows/lane, no barriers =======
    // lane l at iter t computes col q = t-l+1 for rows 8l+1..8l+8.
    float vnn = 0.0f;
    {
        float mm[8], ww[8], R_[8];
        #pragma unroll
        for (int r = 0; r < 8; ++r) { mm[r] = FBIG; ww[r] = 1.0f; R_[r] = FBIG; }
        float shAm = FBIG, shAw = 1.0f, shBm = FBIG, shBw = 1.0f;

        for (int c = 0; c < TT / 8; ++c) {
            #pragma unroll
            for (int k = 0; k < 8; ++k) {
                const int t = c * 8 + k;
                const int q = t - l + 1;
                const bool act   = (unsigned)(t - l) < NN;
                const bool first = (t == l);
                if (first) {
                    #pragma unroll
                    for (int r = 0; r < 8; ++r) { mm[r] = FBIG; ww[r] = 1.0f; }
                }
                float um = (l == 0) ? FBIG : shAm;    // up row, col q (raw m,w)
                float uw = (l == 0) ? 1.0f : shAw;
                float dm = (l == 0) ? FBIG : shBm;    // up row, col q-1
                float dw = (l == 0) ? 1.0f : shBw;
                if (first) { dm = (l == 0) ? 0.0f : FBIG; dw = 1.0f; } // V[0][0]=0
                float oj = s_o[act ? (q - 1) : 0];
                float pm = um, pw = uw, pdm = dm, pdw = dw;
                #pragma unroll
                for (int r = 0; r < 8; ++r) {
                    float ms  = fminf(mm[r], fminf(pm, pdm));
                    float msK = ms * K2;
                    float eo  = ex2(fmaf(-K2, mm[r], msK));
                    float eu  = ex2(fmaf(-K2, pm,   msK));
                    float ed  = ex2(fmaf(-K2, pdm,  msK));
                    float nw  = fmaf(ww[r], eo, fmaf(pw, eu, pdw * ed));
                    float df  = ti[r] - oj;
                    float nm  = fmaf(df, df, ms);
                    R_[r] = fmaf(-GLN2, lg2(nw), nm);   // folded V (off m-chain)
                    pdm = mm[r]; pdw = ww[r];           // next row's diag = old
                    mm[r] = nm;  ww[r] = nw;
                    pm = nm;     pw = nw;               // next row's up = new
                }
                if (act) {
                    float4* p = Rbase + (((t << 5) + l) << 1);
                    p[0] = make_float4(R_[0], R_[1], R_[2], R_[3]);
                    p[1] = make_float4(R_[4], R_[5], R_[6], R_[7]);
                    if (l == 31 && q == NN) vnn = R_[7];   // V[N][N]
                }
                float pEm = act ? mm[7] : FBIG;   // raw (m,w) handoff
                float pEw = act ? ww[7] : 1.0f;
                shBm = shAm; shBw = shAw;
                shAm = __shfl_up_sync(FULL, pEm, 1);
                shAw = __shfl_up_sync(FULL, pEw, 1);
            }
            // renormalize every 8 cols: (m,w) <- (folded V, 1). Bounds w in [1,3^8].
            #pragma unroll
            for (int r = 0; r < 8; ++r) { mm[r] = R_[r]; ww[r] = 1.0f; }
        }
    }
    __syncthreads();   // forward stores (all lanes) visible before backward loads

    // ================= BACKWARD: mirrored forward, 8 rows/lane =================
    // Reversed p=N+1-i, q'=N+1-j. Lane l owns p-rows 8l+1..8l+8 (orig group 31-l,
    // reversed row r <-> stored component 7-r). Linear E recurrence (fma chain).
    float sumE = 0.0f;
    {
        float tP[8];
        #pragma unroll
        for (int r = 0; r < 8; ++r) tP[r] = s_t[255 - 8 * l - r];  // T'(p0+r)
        const float tU = s_t[(l == 0) ? 0 : (256 - 8 * l)];        // T'(p0-1); unused l==0

        float e_[8], rr_[8];
        #pragma unroll
        for (int r = 0; r < 8; ++r) { e_[r] = 0.0f; rr_[r] = NBIG; }
        float shEA = 0.0f, shRA = NBIG, shEB = 0.0f, shRB = NBIG;
        float oqm1 = 0.0f;
        float4 rcA[4], rcB[4], rnA[4], rnB[4];

        #pragma unroll
        for (int k = 0; k < 4; ++k) {   // prefetch chunk 0
            int t = k; bool a = (unsigned)(t - l) < NN;
            const float4* p = Rbase + (((((NN + 30 - t) << 5)) + (31 - l)) << 1);
            rcA[k] = a ? __ldg(p)     : make_float4(NBIG, NBIG, NBIG, NBIG);
            rcB[k] = a ? __ldg(p + 1) : make_float4(NBIG, NBIG, NBIG, NBIG);
        }

        for (int c = 0; c < TT / 4; ++c) {
            if (c + 1 < TT / 4) {       // prefetch next chunk (overlaps compute)
                #pragma unroll
                for (int k = 0; k < 4; ++k) {
                    int t = (c + 1) * 4 + k; bool a = (unsigned)(t - l) < NN;
                    const float4* p = Rbase + (((((NN + 30 - t) << 5)) + (31 - l)) << 1);
                    rnA[k] = a ? __ldg(p)     : make_float4(NBIG, NBIG, NBIG, NBIG);
                    rnB[k] = a ? __ldg(p + 1) : make_float4(NBIG, NBIG, NBIG, NBIG);
                }
            }
            #pragma unroll
            for (int k = 0; k < 4; ++k) {
                const int t = c * 4 + k;
                const int q = t - l + 1;
                const bool act   = (unsigned)(t - l) < NN;
                const bool first = (t == l);
                if (first) {
                    #pragma unroll
                    for (int r = 0; r < 8; ++r) { e_[r] = 0.0f; rr_[r] = NBIG; }
                }
                float Eu = (l == 0) ? 0.0f : shEA;
                float Ru = (l == 0) ? NBIG : shRA;
                float Ed = (l == 0) ? 0.0f : shEB;
                float Rd = (l == 0) ? NBIG : shRB;
                if (first) { Ed = 0.0f; Rd = NBIG; }
                float oq = s_o[act ? (NN - q) : 0];   // o'_{q'}
                float Rc[8];
                Rc[0] = rcB[k].w; Rc[1] = rcB[k].z; Rc[2] = rcB[k].y; Rc[3] = rcB[k].x;
                Rc[4] = rcA[k].w; Rc[5] = rcA[k].z; Rc[6] = rcA[k].y; Rc[7] = rcA[k].x;
                float pe = Eu, pr = Ru, pde = Ed, pdr = Rd;
                #pragma unroll
                for (int r = 0; r < 8; ++r) {
                    float tUp = (r == 0) ? tU : tP[r - 1];
                    float dU = tUp   - oq;
                    float dL = tP[r] - oqm1;
                    float dD = tUp   - oqm1;
                    float a1 = ex2(fmaf(-dU, dU, pr     - Rc[r]) * K2);
                    float a2 = ex2(fmaf(-dL, dL, rr_[r] - Rc[r]) * K2);
                    float a3 = ex2(fmaf(-dD, dD, pdr    - Rc[r]) * K2);
                    float nv = fmaf(a1, pe, fmaf(a2, e_[r], a3 * pde));
                    if (r == 0 && l == 0 && t == 0) nv = 1.0f;    // E[N][N]
                    pde = e_[r]; pdr = rr_[r];        // next row diag = old
                    e_[r] = nv;  rr_[r] = Rc[r];
                    pe = nv;     pr = Rc[r];          // next row up = new
                }
                if (!act) {
                    #pragma unroll
                    for (int r = 0; r < 8; ++r) { e_[r] = 0.0f; rr_[r] = NBIG; }
                }
                if (act) {
                    float wqb = (float)(t - 9 * l);   // (i-j) for row0
                    #pragma unroll
                    for (int r = 0; r < 8; ++r) {
                        float wq = wqb - (float)r;
                        sumE = fmaf(e_[r], wq * wq, sumE);
                    }
                }
                float pE = act ? e_[7]  : 0.0f;
                float pR = act ? rr_[7] : NBIG;
                shEB = shEA; shRB = shRA;
                shEA = __shfl_up_sync(FULL, pE, 1);
                shRA = __shfl_up_sync(FULL, pR, 1);
                oqm1 = oq;
            }
            #pragma unroll
            for (int k = 0; k < 4; ++k) { rcA[k] = rnA[k]; rcB[k] = rnB[k]; }
        }
    }

    // ---- warp reductions + deterministic last-block finalize ----
    #pragma unroll
    for (int off = 16; off > 0; off >>= 1)
        sumE += __shfl_down_sync(FULL, sumE, off);
    float vnn31 = __shfl_sync(FULL, vnn, 31);

    int last = 0;
    if (l == 0) {
        g_partV[b] = vnn31;
        g_partE[b] = sumE;
        __threadfence();
        last = (atomicAdd(&g_ticket, 1u) == BB - 1) ? 1 : 0;
    }
    last = __shfl_sync(FULL, last, 0);
    if (last) {
        __threadfence();
        float sv = __ldcg(&g_partV[l]) + __ldcg(&g_partV[l + 32]);
        float se = __ldcg(&g_partE[l]) + __ldcg(&g_partE[l + 32]);
        #pragma unroll
        for (int off = 16; off > 0; off >>= 1) {
            sv += __shfl_down_sync(FULL, sv, off);
            se += __shfl_down_sync(FULL, se, off);
        }
        if (l == 0) {
            float loss_shape    = sv * (1.0f / (float)BB);
            float loss_temporal = se * (1.0f / ((float)BB * (float)(NN * NN)));
            out[0] = 0.5f * loss_shape + 0.5f * loss_temporal;
            g_ticket = 0;   // reset for graph replay
        }
    }
}

extern "C" void kernel_launch(void* const* d_in, const int* in_sizes, int n_in,
                              void* d_out, int out_size) {
    const float* y_pred = (const float*)d_in[0];
    const float* y_true = (const float*)d_in[1];
    dilate_fb_kernel<<<BB, 32>>>(y_pred, y_true, (float*)d_out);
}

// round 11
// speedup vs baseline: 2.9655x; 1.3103x over previous
#include <cuda_runtime.h>

#define NN 256
#define BB 64
#define FBIG 1e8f
#define NBIG (-1e8f)
#define K2   144.269504089f     // (1/gamma) * log2(e), gamma = 0.01
#define GLN2 0.006931471806f    // gamma * ln(2)
#define TT   320                // 40 chunks x 8 iters (>= 319 needed)
#define FULL 0xffffffffu

// R scratch, time-major: idx = t*64 + V (V = virtual lane = 4-row group).
// Forward STG and backward mirror LDG are both warp-contiguous. 21 MB -> L2.
__device__ float4 g_R4[BB * TT * 64];
__device__ float g_partV[BB];
__device__ float g_partE[BB];
__device__ unsigned g_ticket = 0;

__device__ __forceinline__ float ex2(float x) { float r; asm("ex2.approx.f32 %0, %1;" : "=f"(r) : "f"(x)); return r; }
__device__ __forceinline__ float lg2(float x) { float r; asm("lg2.approx.f32 %0, %1;" : "=f"(r) : "f"(x)); return r; }

__global__ __launch_bounds__(64, 1) void dilate_fb_kernel(
    const float* __restrict__ y_pred,
    const float* __restrict__ y_true,
    float* __restrict__ out)
{
    __shared__ float s_o[NN], s_t[NN];
    __shared__ float s_fh;            // fwd cross-warp handoff (folded V)
    __shared__ float s_he, s_hr;      // bwd cross-warp handoff (E, R)
    __shared__ float s_red[2];
    __shared__ float s_vnn;
    __shared__ int   s_last;

    const int b   = blockIdx.x;
    const int tid = threadIdx.x;      // virtual lane V = tid; rows 4V+1..4V+4
    const int w   = tid >> 5;
    const int l   = tid & 31;

    for (int x = tid; x < NN; x += 64) {
        s_o[x] = y_pred[b * NN + x];
        s_t[x] = y_true[b * NN + x];
    }
    if (tid == 0) { s_fh = FBIG; s_he = 0.0f; s_hr = NBIG; }
    __syncthreads();

    const float ti0 = s_t[4 * tid];
    const float ti1 = s_t[4 * tid + 1];
    const float ti2 = s_t[4 * tid + 2];
    const float ti3 = s_t[4 * tid + 3];
    float4* __restrict__ Rb = g_R4 + (size_t)b * (TT * 64);

    // ================= FORWARD: (m,w) soft-min, 4 rows/lane, 64-lane ladder ======
    // virtual lane V at iter t computes col q = t-V+1 for rows 4V+1..4V+4.
    {
        float mm0 = FBIG, mm1 = FBIG, mm2 = FBIG, mm3 = FBIG;
        float ww0 = 1.0f, ww1 = 1.0f, ww2 = 1.0f, ww3 = 1.0f;
        float R0 = FBIG, R1 = FBIG, R2 = FBIG, R3 = FBIG;
        float shA = FBIG, shB = FBIG;   // intra-warp pipeline (lane l-1 folded row-4)
        float lzu = FBIG, lzd = FBIG;   // cross-warp pipeline (w1 lane0)

        for (int c = 0; c < TT / 8; ++c) {
            float o_pre[8];
            #pragma unroll
            for (int k = 0; k < 8; ++k) {
                int x = c * 8 + k - tid;
                x = min(max(x, 0), NN - 1);
                o_pre[k] = s_o[x];
            }
            #pragma unroll
            for (int k = 0; k < 8; ++k) {
                const int t = c * 8 + k;
                const bool act   = (unsigned)(t - tid) < NN;
                const bool first = (t == tid);
                if (first) { mm0 = FBIG; mm1 = FBIG; mm2 = FBIG; mm3 = FBIG;
                             ww0 = 1.0f; ww1 = 1.0f; ww2 = 1.0f; ww3 = 1.0f; }
                float up, dg;
                if (l == 0) { up = (w == 0) ? FBIG : lzu; dg = (w == 0) ? FBIG : lzd; }
                else        { up = shA;                    dg = shB; }
                if (first) dg = (tid == 0) ? 0.0f : FBIG;   // V[0][0]=0 boundary
                float oj = o_pre[k];
                // row0 (up/diag folded, weight 1)
                float ms0 = fminf(mm0, fminf(up, dg));
                float k0  = ms0 * K2;
                float nw0 = fmaf(ww0, ex2(fmaf(-K2, mm0, k0)),
                                 ex2(fmaf(-K2, up, k0)) + ex2(fmaf(-K2, dg, k0)));
                float d0  = ti0 - oj;
                float nm0 = fmaf(d0, d0, ms0);
                // row1: up=(nm0,nw0) cur, diag=(mm0,ww0) old
                float ms1 = fminf(mm1, fminf(nm0, mm0));
                float k1  = ms1 * K2;
                float nw1 = fmaf(ww1, ex2(fmaf(-K2, mm1, k1)),
                            fmaf(nw0, ex2(fmaf(-K2, nm0, k1)),
                                 ww0 * ex2(fmaf(-K2, mm0, k1))));
                float d1  = ti1 - oj;
                float nm1 = fmaf(d1, d1, ms1);
                // row2
                float ms2 = fminf(mm2, fminf(nm1, mm1));
                float k2_ = ms2 * K2;
                float nw2 = fmaf(ww2, ex2(fmaf(-K2, mm2, k2_)),
                            fmaf(nw1, ex2(fmaf(-K2, nm1, k2_)),
                                 ww1 * ex2(fmaf(-K2, mm1, k2_))));
                float d2  = ti2 - oj;
                float nm2 = fmaf(d2, d2, ms2);
                // row3
                float ms3 = fminf(mm3, fminf(nm2, mm2));
                float k3  = ms3 * K2;
                float nw3 = fmaf(ww3, ex2(fmaf(-K2, mm3, k3)),
                            fmaf(nw2, ex2(fmaf(-K2, nm2, k3)),
                                 ww2 * ex2(fmaf(-K2, mm2, k3))));
                float d3  = ti3 - oj;
                float nm3 = fmaf(d3, d3, ms3);
                // fold (off the m-chain)
                R0 = fmaf(-GLN2, lg2(nw0), nm0);
                R1 = fmaf(-GLN2, lg2(nw1), nm1);
                R2 = fmaf(-GLN2, lg2(nw2), nm2);
                R3 = fmaf(-GLN2, lg2(nw3), nm3);
                if (act) {
                    Rb[t * 64 + tid] = make_float4(R0, R1, R2, R3);
                    if (tid == 63 && t == NN + 62) s_vnn = R3;   // V[N][N]
                }
                float hp = act ? R3 : FBIG;
                float sh = __shfl_up_sync(FULL, hp, 1);
                shB = shA; shA = sh;
                if (tid == 31) s_fh = hp;
                __syncthreads();
                if (w == 1) { lzd = lzu; lzu = s_fh; }
                mm0 = nm0; ww0 = nw0; mm1 = nm1; ww1 = nw1;
                mm2 = nm2; ww2 = nw2; mm3 = nm3; ww3 = nw3;
            }
            // renormalize every 8 cols (w <= 3^8): m <- folded V, w <- 1
            mm0 = R0; mm1 = R1; mm2 = R2; mm3 = R3;
            ww0 = 1.0f; ww1 = 1.0f; ww2 = 1.0f; ww3 = 1.0f;
        }
    }

    // ================= BACKWARD: mirrored forward, 4 rows/lane ===================
    // Reversed p=N+1-i, q'=N+1-j; lane V owns p-rows 4V+1..4V+4 = orig group 63-V
    // (component r <-> 3-r). R for reversed iter t is at (NN+62-t)*64 + (63-V).
    float sumE = 0.0f;
    {
        const float tP0 = s_t[255 - 4 * tid];
        const float tP1 = s_t[254 - 4 * tid];
        const float tP2 = s_t[253 - 4 * tid];
        const float tP3 = s_t[252 - 4 * tid];
        const float tU  = s_t[min(256 - 4 * tid, 255)];   // T'(p0-1); unused V==0

        float e0 = 0, e1 = 0, e2 = 0, e3 = 0;
        float r0 = NBIG, r1 = NBIG, r2 = NBIG, r3 = NBIG;
        float shEA = 0, shEB = 0, shRA = NBIG, shRB = NBIG;
        float lzEu = 0, lzEd = 0, lzRu = NBIG, lzRd = NBIG;
        float oqm1 = 0.0f;
        const int bwoff = 63 - tid;
        float4 rc[8], rn[8];

        #pragma unroll
        for (int k = 0; k < 8; ++k) {   // prefetch chunk 0
            int t = k; bool a = (unsigned)(t - tid) < NN;
            rc[k] = a ? __ldg(Rb + (NN + 62 - t) * 64 + bwoff)
                      : make_float4(NBIG, NBIG, NBIG, NBIG);
        }

        for (int c = 0; c < TT / 8; ++c) {
            if (c + 1 < TT / 8) {       // prefetch next chunk (overlaps compute)
                #pragma unroll
                for (int k = 0; k < 8; ++k) {
                    int t = (c + 1) * 8 + k; bool a = (unsigned)(t - tid) < NN;
                    rn[k] = a ? __ldg(Rb + (NN + 62 - t) * 64 + bwoff)
                              : make_float4(NBIG, NBIG, NBIG, NBIG);
                }
            }
            float o_pre[8];
            #pragma unroll
            for (int k = 0; k < 8; ++k) {
                int x = NN - 1 - (c * 8 + k - tid);
                x = min(max(x, 0), NN - 1);
                o_pre[k] = s_o[x];
            }
            #pragma unroll
            for (int k = 0; k < 8; ++k) {
                const int t = c * 8 + k;
                const bool act   = (unsigned)(t - tid) < NN;
                const bool first = (t == tid);
                if (first) { e0 = e1 = e2 = e3 = 0.0f; r0 = r1 = r2 = r3 = NBIG; }
                float Eu, Ru, Ed, Rd;
                if (l == 0) { Eu = (w == 0) ? 0.0f : lzEu; Ru = (w == 0) ? NBIG : lzRu;
                              Ed = (w == 0) ? 0.0f : lzEd; Rd = (w == 0) ? NBIG : lzRd; }
                else        { Eu = shEA; Ru = shRA; Ed = shEB; Rd = shRB; }
                if (first) { Ed = 0.0f; Rd = NBIG; }
                float oq = o_pre[k];
                float4 Rc = rc[k];
                float Rc0 = Rc.w, Rc1 = Rc.z, Rc2 = Rc.y, Rc3 = Rc.x;
                // row0 (p0)
                float dU0 = tU - oq, dL0 = tP0 - oqm1, dD0 = tU - oqm1;
                float ne0 = fmaf(ex2(fmaf(-dU0, dU0, Ru - Rc0) * K2), Eu,
                            fmaf(ex2(fmaf(-dL0, dL0, r0 - Rc0) * K2), e0,
                                 ex2(fmaf(-dD0, dD0, Rd - Rc0) * K2) * Ed));
                if (tid == 0 && t == 0) ne0 = 1.0f;   // E[N][N]
                // row1: up=(Rc0,ne0) cur; diag=(r0,e0) old
                float dU1 = tP0 - oq, dL1 = tP1 - oqm1, dD1 = tP0 - oqm1;
                float ne1 = fmaf(ex2(fmaf(-dU1, dU1, Rc0 - Rc1) * K2), ne0,
                            fmaf(ex2(fmaf(-dL1, dL1, r1 - Rc1) * K2), e1,
                                 ex2(fmaf(-dD1, dD1, r0 - Rc1) * K2) * e0));
                // row2
                float dU2 = tP1 - oq, dL2 = tP2 - oqm1, dD2 = tP1 - oqm1;
                float ne2 = fmaf(ex2(fmaf(-dU2, dU2, Rc1 - Rc2) * K2), ne1,
                            fmaf(ex2(fmaf(-dL2, dL2, r2 - Rc2) * K2), e2,
                                 ex2(fmaf(-dD2, dD2, r1 - Rc2) * K2) * e1));
                // row3
                float dU3 = tP2 - oq, dL3 = tP3 - oqm1, dD3 = tP2 - oqm1;
                float ne3 = fmaf(ex2(fmaf(-dU3, dU3, Rc2 - Rc3) * K2), ne2,
                            fmaf(ex2(fmaf(-dL3, dL3, r3 - Rc3) * K2), e3,
                                 ex2(fmaf(-dD3, dD3, r2 - Rc3) * K2) * e2));
                if (!act) { ne0 = 0; ne1 = 0; ne2 = 0; ne3 = 0;
                            Rc0 = NBIG; Rc1 = NBIG; Rc2 = NBIG; Rc3 = NBIG; }
                if (act) {
                    float wq = (float)(t - 5 * tid);    // (i-j) for row0
                    sumE = fmaf(ne0, wq * wq, sumE);
                    float w1_ = wq - 1.0f; sumE = fmaf(ne1, w1_ * w1_, sumE);
                    float w2_ = wq - 2.0f; sumE = fmaf(ne2, w2_ * w2_, sumE);
                    float w3_ = wq - 3.0f; sumE = fmaf(ne3, w3_ * w3_, sumE);
                }
                float hpE = ne3, hpR = Rc3;
                float sE = __shfl_up_sync(FULL, hpE, 1);
                float sR = __shfl_up_sync(FULL, hpR, 1);
                shEB = shEA; shEA = sE;
                shRB = shRA; shRA = sR;
                if (tid == 31) { s_he = hpE; s_hr = hpR; }
                __syncthreads();
                if (w == 1) { lzEd = lzEu; lzRd = lzRu; lzEu = s_he; lzRu = s_hr; }
                e0 = ne0; e1 = ne1; e2 = ne2; e3 = ne3;
                r0 = Rc0; r1 = Rc1; r2 = Rc2; r3 = Rc3;
                oqm1 = oq;
            }
            #pragma unroll
            for (int k = 0; k < 8; ++k) rc[k] = rn[k];
        }
    }

    // ---- reduce sum(E * omega) ----
    #pragma unroll
    for (int off = 16; off > 0; off >>= 1)
        sumE += __shfl_down_sync(FULL, sumE, off);
    if (l == 0) s_red[w] = sumE;
    __syncthreads();

    if (tid == 0) {
        g_partV[b] = s_vnn;
        g_partE[b] = s_red[0] + s_red[1];
        __threadfence();
        unsigned tk = atomicAdd(&g_ticket, 1u);
        s_last = (tk == BB - 1) ? 1 : 0;
    }
    __syncthreads();
    if (s_last && tid < 32) {
        __threadfence();
        float sv = __ldcg(&g_partV[tid]) + __ldcg(&g_partV[tid + 32]);
        float se = __ldcg(&g_partE[tid]) + __ldcg(&g_partE[tid + 32]);
        #pragma unroll
        for (int off = 16; off > 0; off >>= 1) {
            sv += __shfl_down_sync(FULL, sv, off);
            se += __shfl_down_sync(FULL, se, off);
        }
        if (tid == 0) {
            float loss_shape    = sv * (1.0f / (float)BB);
            float loss_temporal = se * (1.0f / ((float)BB * (float)(NN * NN)));
            out[0] = 0.5f * loss_shape + 0.5f * loss_temporal;
            g_ticket = 0;   // reset for graph replay
        }
    }
}

extern "C" void kernel_launch(void* const* d_in, const int* in_sizes, int n_in,
                              void* d_out, int out_size) {
    const float* y_pred = (const float*)d_in[0];
    const float* y_true = (const float*)d_in[1];
    dilate_fb_kernel<<<BB, 64>>>(y_pred, y_true, (float*)d_out);
}